// round 14
// baseline (speedup 1.0000x reference)
#include <cuda_runtime.h>

#define ALPHA 0.2f
#define MASKV -9000000000000000.0f
using ull  = unsigned long long;
using ull2 = ulonglong2;

__constant__ __align__(16) float cW1[96];     // (3,1,32)
__constant__ __align__(16) float cA1[192];    // (3,64,1)
__constant__ __align__(16) float cW2[4608];   // (3,96,16)
__constant__ __align__(16) float cA2[96];     // (3,32,1)
__constant__ __align__(16) float cWp1[1152];  // (48,24)
__constant__ __align__(16) float cBp1[24];
__constant__ __align__(16) float cWp2[24];
__constant__ __align__(16) float cBp2[4];
__constant__ __align__(16) float cAdj[84];

#define NTHR 128
#define MAXBLK 1024
#define NT (MAXBLK*NTHR)
#define SSTR 57   // per-thread smem floats: [0..26]=s1, [27..35]=f1, [36..44]=f2

__device__ float    g_c12[6];                 // c1[3], c2[3]
__device__ unsigned g_mrow[9];                // adjacency bitmask per row
// NT-stride scratch (empirically the fastest layout), 16B-vectorized slots
__device__ ull2     g_wh[(size_t)36  * NT];   // Wh head tile: 9 rows x 4 ull2
__device__ ull2     g_h2[(size_t)108 * NT];   // h2: 9 rows x 12 ull2

__device__ __forceinline__ void ffma2(ull& d, ull a, ull b) {
    asm("fma.rn.f32x2 %0, %1, %2, %0;" : "+l"(d) : "l"(a), "l"(b));
}
__device__ __forceinline__ ull dup2(float x) {
    ull r; asm("mov.b64 %0, {%1, %1};" : "=l"(r) : "f"(x)); return r;
}
__device__ __forceinline__ float2 unp(ull v) {
    float2 r; asm("mov.b64 {%0, %1}, %2;" : "=f"(r.x), "=f"(r.y) : "l"(v)); return r;
}
__device__ __forceinline__ float tanh_fast(float x) {
    float r; asm("tanh.approx.f32 %0, %1;" : "=f"(r) : "f"(x)); return r;
}
__device__ __forceinline__ ull c64(const float* p) {
    return __double_as_longlong(*(const double*)(const void*)p);
}
__device__ __forceinline__ float lrelu(float x) { return fmaxf(x, ALPHA * x); }
__device__ __forceinline__ float elu(float x) {
    return (x > 0.f) ? x : (__expf(x) - 1.f);
}

__global__ void prep_kernel() {
    int t = threadIdx.x;
    if (t < 6) {
        int h = t % 3, half = t / 3;
        float s = 0.f;
        #pragma unroll
        for (int d = 0; d < 32; d++)
            s += cW1[h*32 + d] * cA1[h*64 + half*32 + d];
        g_c12[half*3 + h] = s;
    }
    if (t < 9) {
        unsigned m = 0;
        for (int j = 0; j < 9; j++)
            if (cAdj[t*9 + j] > 0.f) m |= (1u << j);
        g_mrow[t] = m;
    }
}

__global__ void __launch_bounds__(NTHR, 4)
gnn_main(const float* __restrict__ g_obs, float* __restrict__ g_out, int B)
{
    __shared__ float sS[NTHR * SSTR];

    const int tid  = threadIdx.x;
    const int gtid = blockIdx.x * NTHR + tid;
    const int stride = gridDim.x * NTHR;
    float* sTp = sS + tid * SSTR;
    ull2*  whb = g_wh + gtid;
    ull2*  h2b = g_h2 + gtid;

    unsigned mrow[9];
    #pragma unroll
    for (int i = 0; i < 9; i++) mrow[i] = __ldg(&g_mrow[i]);
    float c1r[3], c2r[3];
    #pragma unroll
    for (int h = 0; h < 3; h++) { c1r[h] = __ldg(&g_c12[h]); c2r[h] = __ldg(&g_c12[3+h]); }

    for (int b = gtid; b < B; b += stride) {

        // ================= layer-1 (rank-1 collapse): s1[h][i] =================
        {
            float og[9];
            #pragma unroll
            for (int n = 0; n < 9; n++) og[n] = g_obs[b*9 + n];
            #pragma unroll 1
            for (int h = 0; h < 3; h++) {
                const float c1h = c1r[h], c2h = c2r[h];
                float gg[9];
                #pragma unroll
                for (int j = 0; j < 9; j++) gg[j] = c2h * og[j];
                #pragma unroll
                for (int i = 0; i < 9; i++) {
                    const unsigned m = mrow[i];
                    const float fi = c1h * og[i];
                    float e[9], mx = -3.0e38f;
                    #pragma unroll
                    for (int j = 0; j < 9; j++) {
                        float x = lrelu(fi + gg[j]);
                        if (!((m >> j) & 1u)) x = MASKV;
                        e[j] = x; mx = fmaxf(mx, x);
                    }
                    float den = 0.f, num = 0.f;
                    #pragma unroll
                    for (int j = 0; j < 9; j++) {
                        float p = __expf(e[j] - mx);
                        den += p; num += p * og[j];
                    }
                    sTp[h*9 + i] = __fdividef(num, den);
                }
            }
        }

        // ================= layer-2 per head =================
        #pragma unroll 1
        for (int H = 0; H < 3; H++) {
            const float* wH = &cW2[H*1536];

            // ---- GEMM in 3-row passes; f1/f2 from acc·a2 into SMEM ----
            #pragma unroll 1
            for (int g3 = 0; g3 < 9; g3 += 3) {
                ull acc[3][8];
                #pragma unroll
                for (int r = 0; r < 3; r++)
                    #pragma unroll
                    for (int p = 0; p < 8; p++) acc[r][p] = 0ull;

                #pragma unroll 1
                for (int kh = 0; kh < 3; kh++) {
                    const float sA = sTp[kh*9 + g3];
                    const float sB = sTp[kh*9 + g3 + 1];
                    const float sC = sTp[kh*9 + g3 + 2];
                    #pragma unroll 4
                    for (int d = 0; d < 32; d++) {
                        const int k = kh*32 + d;
                        const float w1 = cW1[k];
                        const ull eA = dup2(elu(sA * w1));
                        const ull eB = dup2(elu(sB * w1));
                        const ull eC = dup2(elu(sC * w1));
                        const float* wr = wH + k*16;
                        const ull2 wa = *(const ull2*)(wr);
                        const ull2 wb = *(const ull2*)(wr + 4);
                        const ull2 wc = *(const ull2*)(wr + 8);
                        const ull2 wd = *(const ull2*)(wr + 12);
                        ffma2(acc[0][0], eA, wa.x); ffma2(acc[0][1], eA, wa.y);
                        ffma2(acc[0][2], eA, wb.x); ffma2(acc[0][3], eA, wb.y);
                        ffma2(acc[0][4], eA, wc.x); ffma2(acc[0][5], eA, wc.y);
                        ffma2(acc[0][6], eA, wd.x); ffma2(acc[0][7], eA, wd.y);
                        ffma2(acc[1][0], eB, wa.x); ffma2(acc[1][1], eB, wa.y);
                        ffma2(acc[1][2], eB, wb.x); ffma2(acc[1][3], eB, wb.y);
                        ffma2(acc[1][4], eB, wc.x); ffma2(acc[1][5], eB, wc.y);
                        ffma2(acc[1][6], eB, wd.x); ffma2(acc[1][7], eB, wd.y);
                        ffma2(acc[2][0], eC, wa.x); ffma2(acc[2][1], eC, wa.y);
                        ffma2(acc[2][2], eC, wb.x); ffma2(acc[2][3], eC, wb.y);
                        ffma2(acc[2][4], eC, wc.x); ffma2(acc[2][5], eC, wc.y);
                        ffma2(acc[2][6], eC, wd.x); ffma2(acc[2][7], eC, wd.y);
                    }
                }
                #pragma unroll
                for (int r = 0; r < 3; r++) {
                    float f1 = 0.f, f2 = 0.f;
                    #pragma unroll
                    for (int p = 0; p < 8; p++) {
                        float2 t = unp(acc[r][p]);
                        f1 += t.x * cA2[H*32 + 2*p]      + t.y * cA2[H*32 + 2*p + 1];
                        f2 += t.x * cA2[H*32 + 16 + 2*p] + t.y * cA2[H*32 + 17 + 2*p];
                    }
                    sTp[27 + g3 + r] = f1;
                    sTp[36 + g3 + r] = f2;
                    #pragma unroll
                    for (int q = 0; q < 4; q++) {
                        ull2 v; v.x = acc[r][2*q]; v.y = acc[r][2*q + 1];
                        whb[((g3 + r)*4 + q)*NT] = v;       // 16B store
                    }
                }
            }

            // ---- attention apply for head H (16B Wh loads) ----
            float f2r[9];
            #pragma unroll
            for (int j = 0; j < 9; j++) f2r[j] = sTp[36 + j];

            #pragma unroll 1
            for (int i = 0; i < 9; i++) {
                const unsigned m = mrow[i];
                const float f1i = sTp[27 + i];
                float e[9], mx = -3.0e38f;
                #pragma unroll
                for (int j = 0; j < 9; j++) {
                    float x = lrelu(f1i + f2r[j]);
                    if (!((m >> j) & 1u)) x = MASKV;
                    e[j] = x; mx = fmaxf(mx, x);
                }
                float den = 0.f;
                #pragma unroll
                for (int j = 0; j < 9; j++) { e[j] = __expf(e[j] - mx); den += e[j]; }
                const float inv = __fdividef(1.f, den);

                ull h2a[8];
                #pragma unroll
                for (int p = 0; p < 8; p++) h2a[p] = 0ull;
                #pragma unroll
                for (int j = 0; j < 9; j++) {
                    const ull wd = dup2(e[j] * inv);
                    const ull2 w0 = whb[(j*4 + 0)*NT];
                    const ull2 w1 = whb[(j*4 + 1)*NT];
                    const ull2 w2 = whb[(j*4 + 2)*NT];
                    const ull2 w3 = whb[(j*4 + 3)*NT];
                    ffma2(h2a[0], w0.x, wd); ffma2(h2a[1], w0.y, wd);
                    ffma2(h2a[2], w1.x, wd); ffma2(h2a[3], w1.y, wd);
                    ffma2(h2a[4], w2.x, wd); ffma2(h2a[5], w2.y, wd);
                    ffma2(h2a[6], w3.x, wd); ffma2(h2a[7], w3.y, wd);
                }
                #pragma unroll
                for (int q = 0; q < 4; q++) {
                    ull2 v; v.x = h2a[2*q]; v.y = h2a[2*q + 1];
                    h2b[(i*12 + H*4 + q)*NT] = v;           // 16B store
                }
            }
        }

        // ================= pooling (16B h2 loads) =================
        float scl[9];
        #pragma unroll 1
        for (int n = 0; n < 9; n++) {
            ull U[12];
            #pragma unroll
            for (int mp = 0; mp < 12; mp++) U[mp] = c64(&cBp1[2*mp]);
            #pragma unroll 2
            for (int m2 = 0; m2 < 12; m2++) {
                const ull2 hv2 = h2b[(n*12 + m2)*NT];
                const float2 ha = unp(hv2.x);   // cols 4m2, 4m2+1
                const float2 hb = unp(hv2.y);   // cols 4m2+2, 4m2+3
                const ull hx0 = dup2(ha.x), hx1 = dup2(ha.y);
                const ull hy0 = dup2(hb.x), hy1 = dup2(hb.y);
                #pragma unroll
                for (int mq = 0; mq < 6; mq++) {
                    const ull2 w0 = *(const ull2*)&cWp1[(4*m2    )*24 + 4*mq];
                    const ull2 w1 = *(const ull2*)&cWp1[(4*m2 + 1)*24 + 4*mq];
                    const ull2 w2 = *(const ull2*)&cWp1[(4*m2 + 2)*24 + 4*mq];
                    const ull2 w3 = *(const ull2*)&cWp1[(4*m2 + 3)*24 + 4*mq];
                    ffma2(U[2*mq],     hx0, w0.x); ffma2(U[2*mq + 1], hx0, w0.y);
                    ffma2(U[2*mq],     hx1, w1.x); ffma2(U[2*mq + 1], hx1, w1.y);
                    ffma2(U[2*mq],     hy0, w2.x); ffma2(U[2*mq + 1], hy0, w2.y);
                    ffma2(U[2*mq],     hy1, w3.x); ffma2(U[2*mq + 1], hy1, w3.y);
                }
            }
            float s = cBp2[0];
            #pragma unroll
            for (int mp = 0; mp < 12; mp++) {
                float2 u = unp(U[mp]);
                s += tanh_fast(u.x) * cWp2[2*mp] + tanh_fast(u.y) * cWp2[2*mp + 1];
            }
            scl[n] = s;
        }

        // softmax over nodes
        float mx = scl[0];
        #pragma unroll
        for (int n = 1; n < 9; n++) mx = fmaxf(mx, scl[n]);
        float den = 0.f, wnl[9];
        #pragma unroll
        for (int n = 0; n < 9; n++) { float p = __expf(scl[n] - mx); wnl[n] = p; den += p; }
        const float iv = __fdividef(1.f, den);

        // weighted sum (16B loads) + 16B stores
        ull2 op[12];
        #pragma unroll
        for (int p = 0; p < 12; p++) { op[p].x = 0ull; op[p].y = 0ull; }
        #pragma unroll 1
        for (int n = 0; n < 9; n++) {
            const ull wd = dup2(wnl[n] * iv);
            #pragma unroll
            for (int p = 0; p < 12; p++) {
                const ull2 h = h2b[(n*12 + p)*NT];
                ffma2(op[p].x, h.x, wd);
                ffma2(op[p].y, h.y, wd);
            }
        }
        #pragma unroll
        for (int p = 0; p < 12; p++)
            *(ull2*)&g_out[(size_t)b*48 + 4*p] = op[p];
    }
}

extern "C" void kernel_launch(void* const* d_in, const int* in_sizes, int n_in,
                              void* d_out, int out_size) {
    const float* obs = (const float*)d_in[0];
    int B = in_sizes[0] / 9;

    cudaMemcpyToSymbolAsync(cAdj, d_in[1],   81 * 4, 0, cudaMemcpyDeviceToDevice);
    cudaMemcpyToSymbolAsync(cW1,  d_in[2],   96 * 4, 0, cudaMemcpyDeviceToDevice);
    cudaMemcpyToSymbolAsync(cA1,  d_in[3],  192 * 4, 0, cudaMemcpyDeviceToDevice);
    cudaMemcpyToSymbolAsync(cW2,  d_in[4], 4608 * 4, 0, cudaMemcpyDeviceToDevice);
    cudaMemcpyToSymbolAsync(cA2,  d_in[5],   96 * 4, 0, cudaMemcpyDeviceToDevice);
    cudaMemcpyToSymbolAsync(cWp1, d_in[6], 1152 * 4, 0, cudaMemcpyDeviceToDevice);
    cudaMemcpyToSymbolAsync(cBp1, d_in[7],   24 * 4, 0, cudaMemcpyDeviceToDevice);
    cudaMemcpyToSymbolAsync(cWp2, d_in[8],   24 * 4, 0, cudaMemcpyDeviceToDevice);
    cudaMemcpyToSymbolAsync(cBp2, d_in[9],    1 * 4, 0, cudaMemcpyDeviceToDevice);

    int blocks = (B + NTHR - 1) / NTHR;
    if (blocks > MAXBLK) blocks = MAXBLK;

    prep_kernel<<<1, 32>>>();
    gnn_main<<<blocks, NTHR>>>(obs, (float*)d_out, B);
}

// round 16
// speedup vs baseline: 1.5486x; 1.5486x over previous
#include <cuda_runtime.h>

#define ALPHA 0.2f
#define MASKV -9000000000000000.0f
using ull  = unsigned long long;
using ull2 = ulonglong2;

__constant__ __align__(16) float cW1[96];     // (3,1,32)
__constant__ __align__(16) float cA1[192];    // (3,64,1)
__constant__ __align__(16) float cW2[4608];   // (3,96,16)
__constant__ __align__(16) float cA2[96];     // (3,32,1)
__constant__ __align__(16) float cWp1[1152];  // (48,24)
__constant__ __align__(16) float cBp1[24];
__constant__ __align__(16) float cWp2[24];
__constant__ __align__(16) float cBp2[4];
__constant__ __align__(16) float cAdj[84];

#define NTHR 128
#define MAXBLK 1024
#define NT (MAXBLK*NTHR)
#define SSTR 57   // per-thread smem floats: [0..26]=s1, [27..35]=f1, [36..44]=f2

__device__ float    g_c12[6];                // c1[3], c2[3]
__device__ unsigned g_mrow[9];               // adjacency bitmask per row
__device__ ull      g_wh[(size_t)72  * NT];  // per-head Wh tile (9 rows x 8 pairs)
__device__ ull      g_h2[(size_t)216 * NT];  // h2 pairs (9 rows x 24 pairs)

__device__ __forceinline__ void ffma2(ull& d, ull a, ull b) {
    asm("fma.rn.f32x2 %0, %1, %2, %0;" : "+l"(d) : "l"(a), "l"(b));
}
__device__ __forceinline__ ull dup2(float x) {
    ull r; asm("mov.b64 %0, {%1, %1};" : "=l"(r) : "f"(x)); return r;
}
__device__ __forceinline__ float2 unp(ull v) {
    float2 r; asm("mov.b64 {%0, %1}, %2;" : "=f"(r.x), "=f"(r.y) : "l"(v)); return r;
}
__device__ __forceinline__ float tanh_fast(float x) {
    float r; asm("tanh.approx.f32 %0, %1;" : "=f"(r) : "f"(x)); return r;
}
__device__ __forceinline__ ull c64(const float* p) {
    return __double_as_longlong(*(const double*)(const void*)p);
}
__device__ __forceinline__ float lrelu(float x) { return fmaxf(x, ALPHA * x); }
__device__ __forceinline__ float elu(float x) {
    return (x > 0.f) ? x : (__expf(x) - 1.f);
}

__global__ void prep_kernel() {
    int t = threadIdx.x;
    if (t < 6) {
        int h = t % 3, half = t / 3;
        float s = 0.f;
        #pragma unroll
        for (int d = 0; d < 32; d++)
            s += cW1[h*32 + d] * cA1[h*64 + half*32 + d];
        g_c12[half*3 + h] = s;
    }
    if (t < 9) {
        unsigned m = 0;
        for (int j = 0; j < 9; j++)
            if (cAdj[t*9 + j] > 0.f) m |= (1u << j);
        g_mrow[t] = m;
    }
}

__global__ void __launch_bounds__(NTHR, 4)
gnn_main(const float* __restrict__ g_obs, float* __restrict__ g_out, int B)
{
    __shared__ float sS[NTHR * SSTR];   // per-thread s1/f1/f2 (stride 57, odd)
    __shared__ ull2  sW2h[576];         // W2 cols 0..7 per (H,k): [(H*96+k)*2 + q]

    const int tid  = threadIdx.x;
    const int gtid = blockIdx.x * NTHR + tid;
    const int stride = gridDim.x * NTHR;
    float* sTp = sS + tid * SSTR;
    ull*   whb = g_wh + gtid;
    ull*   h2b = g_h2 + gtid;

    // copy W2 column-half 0..7 into SMEM (cols 8..15 stay on the constant port)
    for (int i = tid; i < 576; i += NTHR) {
        int hk = i >> 1, q = i & 1;     // hk = H*96+k
        sW2h[i] = *(const ull2*)&cW2[hk*16 + q*4];
    }
    __syncthreads();

    unsigned mrow[9];
    #pragma unroll
    for (int i = 0; i < 9; i++) mrow[i] = __ldg(&g_mrow[i]);
    float c1r[3], c2r[3];
    #pragma unroll
    for (int h = 0; h < 3; h++) { c1r[h] = __ldg(&g_c12[h]); c2r[h] = __ldg(&g_c12[3+h]); }

    for (int b = gtid; b < B; b += stride) {

        // ================= layer-1 (rank-1 collapse): s1[h][i] =================
        {
            float og[9];
            #pragma unroll
            for (int n = 0; n < 9; n++) og[n] = g_obs[b*9 + n];
            #pragma unroll 1
            for (int h = 0; h < 3; h++) {
                const float c1h = c1r[h], c2h = c2r[h];
                float gg[9];
                #pragma unroll
                for (int j = 0; j < 9; j++) gg[j] = c2h * og[j];
                #pragma unroll
                for (int i = 0; i < 9; i++) {
                    const unsigned m = mrow[i];
                    const float fi = c1h * og[i];
                    float e[9], mx = -3.0e38f;
                    #pragma unroll
                    for (int j = 0; j < 9; j++) {
                        float x = lrelu(fi + gg[j]);
                        if (!((m >> j) & 1u)) x = MASKV;
                        e[j] = x; mx = fmaxf(mx, x);
                    }
                    float den = 0.f, num = 0.f;
                    #pragma unroll
                    for (int j = 0; j < 9; j++) {
                        float p = __expf(e[j] - mx);
                        den += p; num += p * og[j];
                    }
                    sTp[h*9 + i] = __fdividef(num, den);
                }
            }
        }

        // ================= layer-2 per head =================
        #pragma unroll 1
        for (int H = 0; H < 3; H++) {
            const float* wH  = &cW2[H*1536];
            const ull2*  wHs = sW2h + H*192;

            // ---- GEMM in 3-row passes: cols 0-7 from SMEM, cols 8-15 from const ----
            #pragma unroll 1
            for (int g3 = 0; g3 < 9; g3 += 3) {
                ull acc[3][8];
                #pragma unroll
                for (int r = 0; r < 3; r++)
                    #pragma unroll
                    for (int p = 0; p < 8; p++) acc[r][p] = 0ull;

                #pragma unroll 1
                for (int kh = 0; kh < 3; kh++) {
                    const float sA = sTp[kh*9 + g3];
                    const float sB = sTp[kh*9 + g3 + 1];
                    const float sC = sTp[kh*9 + g3 + 2];
                    #pragma unroll 4
                    for (int d = 0; d < 32; d++) {
                        const int k = kh*32 + d;
                        const float w1 = cW1[k];
                        const ull eA = dup2(elu(sA * w1));
                        const ull eB = dup2(elu(sB * w1));
                        const ull eC = dup2(elu(sC * w1));
                        const ull2 wa = wHs[k*2];                   // LDS: cols 0-3
                        const ull2 wb = wHs[k*2 + 1];               // LDS: cols 4-7
                        const ull2 wc = *(const ull2*)(wH + k*16 + 8);   // LDC: cols 8-11
                        const ull2 wd = *(const ull2*)(wH + k*16 + 12);  // LDC: cols 12-15
                        ffma2(acc[0][0], eA, wa.x); ffma2(acc[0][1], eA, wa.y);
                        ffma2(acc[0][2], eA, wb.x); ffma2(acc[0][3], eA, wb.y);
                        ffma2(acc[0][4], eA, wc.x); ffma2(acc[0][5], eA, wc.y);
                        ffma2(acc[0][6], eA, wd.x); ffma2(acc[0][7], eA, wd.y);
                        ffma2(acc[1][0], eB, wa.x); ffma2(acc[1][1], eB, wa.y);
                        ffma2(acc[1][2], eB, wb.x); ffma2(acc[1][3], eB, wb.y);
                        ffma2(acc[1][4], eB, wc.x); ffma2(acc[1][5], eB, wc.y);
                        ffma2(acc[1][6], eB, wd.x); ffma2(acc[1][7], eB, wd.y);
                        ffma2(acc[2][0], eC, wa.x); ffma2(acc[2][1], eC, wa.y);
                        ffma2(acc[2][2], eC, wb.x); ffma2(acc[2][3], eC, wb.y);
                        ffma2(acc[2][4], eC, wc.x); ffma2(acc[2][5], eC, wc.y);
                        ffma2(acc[2][6], eC, wd.x); ffma2(acc[2][7], eC, wd.y);
                    }
                }
                #pragma unroll
                for (int r = 0; r < 3; r++) {
                    float f1 = 0.f, f2 = 0.f;
                    #pragma unroll
                    for (int p = 0; p < 8; p++) {
                        float2 t = unp(acc[r][p]);
                        f1 += t.x * cA2[H*32 + 2*p]      + t.y * cA2[H*32 + 2*p + 1];
                        f2 += t.x * cA2[H*32 + 16 + 2*p] + t.y * cA2[H*32 + 17 + 2*p];
                    }
                    sTp[27 + g3 + r] = f1;
                    sTp[36 + g3 + r] = f2;
                    #pragma unroll
                    for (int p = 0; p < 8; p++)
                        whb[((g3 + r)*8 + p)*NT] = acc[r][p];
                }
            }

            // ---- attention apply for head H ----
            float f2r[9];
            #pragma unroll
            for (int j = 0; j < 9; j++) f2r[j] = sTp[36 + j];

            #pragma unroll 1
            for (int i = 0; i < 9; i++) {
                const unsigned m = mrow[i];
                const float f1i = sTp[27 + i];
                float e[9], mx = -3.0e38f;
                #pragma unroll
                for (int j = 0; j < 9; j++) {
                    float x = lrelu(f1i + f2r[j]);
                    if (!((m >> j) & 1u)) x = MASKV;
                    e[j] = x; mx = fmaxf(mx, x);
                }
                float den = 0.f;
                #pragma unroll
                for (int j = 0; j < 9; j++) { e[j] = __expf(e[j] - mx); den += e[j]; }
                const float inv = __fdividef(1.f, den);

                ull h2a[8];
                #pragma unroll
                for (int p = 0; p < 8; p++) h2a[p] = 0ull;
                #pragma unroll
                for (int j = 0; j < 9; j++) {
                    const ull wd = dup2(e[j] * inv);
                    #pragma unroll
                    for (int p = 0; p < 8; p++)
                        ffma2(h2a[p], whb[(j*8 + p)*NT], wd);
                }
                #pragma unroll
                for (int p = 0; p < 8; p++)
                    h2b[(i*24 + H*8 + p)*NT] = h2a[p];
            }
        }

        // ================= pooling =================
        float scl[9];
        #pragma unroll 1
        for (int n = 0; n < 9; n++) {
            ull U[12];
            #pragma unroll
            for (int mp = 0; mp < 12; mp++) U[mp] = c64(&cBp1[2*mp]);
            #pragma unroll 4
            for (int cp = 0; cp < 24; cp++) {
                float2 hv = unp(h2b[(n*24 + cp)*NT]);
                ull hx = dup2(hv.x), hy = dup2(hv.y);
                #pragma unroll
                for (int mq = 0; mq < 6; mq++) {
                    ull2 wa = *(const ull2*)&cWp1[(2*cp    )*24 + 4*mq];
                    ull2 wb = *(const ull2*)&cWp1[(2*cp + 1)*24 + 4*mq];
                    ffma2(U[2*mq],     hx, wa.x);
                    ffma2(U[2*mq + 1], hx, wa.y);
                    ffma2(U[2*mq],     hy, wb.x);
                    ffma2(U[2*mq + 1], hy, wb.y);
                }
            }
            float s = cBp2[0];
            #pragma unroll
            for (int mp = 0; mp < 12; mp++) {
                float2 u = unp(U[mp]);
                s += tanh_fast(u.x) * cWp2[2*mp] + tanh_fast(u.y) * cWp2[2*mp + 1];
            }
            scl[n] = s;
        }

        // softmax over nodes
        float mx = scl[0];
        #pragma unroll
        for (int n = 1; n < 9; n++) mx = fmaxf(mx, scl[n]);
        float den = 0.f, wnl[9];
        #pragma unroll
        for (int n = 0; n < 9; n++) { float p = __expf(scl[n] - mx); wnl[n] = p; den += p; }
        const float iv = __fdividef(1.f, den);

        ull outp[24];
        #pragma unroll
        for (int p = 0; p < 24; p++) outp[p] = 0ull;
        #pragma unroll 1
        for (int n = 0; n < 9; n++) {
            const ull wd = dup2(wnl[n] * iv);
            #pragma unroll
            for (int p = 0; p < 24; p++)
                ffma2(outp[p], h2b[(n*24 + p)*NT], wd);
        }
        #pragma unroll
        for (int p = 0; p < 24; p++)
            *(ull*)&g_out[(size_t)b*48 + 2*p] = outp[p];
    }
}

extern "C" void kernel_launch(void* const* d_in, const int* in_sizes, int n_in,
                              void* d_out, int out_size) {
    const float* obs = (const float*)d_in[0];
    int B = in_sizes[0] / 9;

    cudaMemcpyToSymbolAsync(cAdj, d_in[1],   81 * 4, 0, cudaMemcpyDeviceToDevice);
    cudaMemcpyToSymbolAsync(cW1,  d_in[2],   96 * 4, 0, cudaMemcpyDeviceToDevice);
    cudaMemcpyToSymbolAsync(cA1,  d_in[3],  192 * 4, 0, cudaMemcpyDeviceToDevice);
    cudaMemcpyToSymbolAsync(cW2,  d_in[4], 4608 * 4, 0, cudaMemcpyDeviceToDevice);
    cudaMemcpyToSymbolAsync(cA2,  d_in[5],   96 * 4, 0, cudaMemcpyDeviceToDevice);
    cudaMemcpyToSymbolAsync(cWp1, d_in[6], 1152 * 4, 0, cudaMemcpyDeviceToDevice);
    cudaMemcpyToSymbolAsync(cBp1, d_in[7],   24 * 4, 0, cudaMemcpyDeviceToDevice);
    cudaMemcpyToSymbolAsync(cWp2, d_in[8],   24 * 4, 0, cudaMemcpyDeviceToDevice);
    cudaMemcpyToSymbolAsync(cBp2, d_in[9],    1 * 4, 0, cudaMemcpyDeviceToDevice);

    int blocks = (B + NTHR - 1) / NTHR;
    if (blocks > MAXBLK) blocks = MAXBLK;

    prep_kernel<<<1, 32>>>();
    gnn_main<<<blocks, NTHR>>>(obs, (float*)d_out, B);
}

// round 17
// speedup vs baseline: 1.5809x; 1.0208x over previous
#include <cuda_runtime.h>

#define ALPHA 0.2f
#define MASKV -9000000000000000.0f
using ull  = unsigned long long;
using ull2 = ulonglong2;

__constant__ __align__(16) float cW1[96];     // (3,1,32)
__constant__ __align__(16) float cA1[192];    // (3,64,1)
__constant__ __align__(16) float cW2[4608];   // (3,96,16)
__constant__ __align__(16) float cA2[96];     // (3,32,1)
__constant__ __align__(16) float cWp1[1152];  // (48,24)
__constant__ __align__(16) float cBp1[24];
__constant__ __align__(16) float cWp2[24];
__constant__ __align__(16) float cBp2[4];
__constant__ __align__(16) float cAdj[84];

#define NTHR 128
#define MAXBLK 1024
#define NT (MAXBLK*NTHR)
#define SSTR 57   // per-thread smem floats: [0..26]=s1, [27..35]=f1, [36..44]=f2

__device__ float    g_c12[6];                // c1[3], c2[3]
__device__ unsigned g_mrow[9];               // adjacency bitmask per row
__device__ ull      g_wh[(size_t)72  * NT];  // per-head Wh tile (9 rows x 8 pairs)
__device__ ull      g_h2[(size_t)216 * NT];  // h2 pairs (9 rows x 24 pairs)

__device__ __forceinline__ void ffma2(ull& d, ull a, ull b) {
    asm("fma.rn.f32x2 %0, %1, %2, %0;" : "+l"(d) : "l"(a), "l"(b));
}
__device__ __forceinline__ ull dup2(float x) {
    ull r; asm("mov.b64 %0, {%1, %1};" : "=l"(r) : "f"(x)); return r;
}
__device__ __forceinline__ float2 unp(ull v) {
    float2 r; asm("mov.b64 {%0, %1}, %2;" : "=f"(r.x), "=f"(r.y) : "l"(v)); return r;
}
__device__ __forceinline__ float tanh_fast(float x) {
    float r; asm("tanh.approx.f32 %0, %1;" : "=f"(r) : "f"(x)); return r;
}
__device__ __forceinline__ ull c64(const float* p) {
    return __double_as_longlong(*(const double*)(const void*)p);
}
__device__ __forceinline__ float lrelu(float x) { return fmaxf(x, ALPHA * x); }
__device__ __forceinline__ float elu(float x) {
    return (x > 0.f) ? x : (__expf(x) - 1.f);
}

__global__ void prep_kernel() {
    int t = threadIdx.x;
    if (t < 6) {
        int h = t % 3, half = t / 3;
        float s = 0.f;
        #pragma unroll
        for (int d = 0; d < 32; d++)
            s += cW1[h*32 + d] * cA1[h*64 + half*32 + d];
        g_c12[half*3 + h] = s;
    }
    if (t < 9) {
        unsigned m = 0;
        for (int j = 0; j < 9; j++)
            if (cAdj[t*9 + j] > 0.f) m |= (1u << j);
        g_mrow[t] = m;
    }
}

__global__ void __launch_bounds__(NTHR, 4)
gnn_main(const float* __restrict__ g_obs, float* __restrict__ g_out, int B)
{
    __shared__ float sS[NTHR * SSTR];   // per-thread s1[27]/f1/f2 (stride 57, odd)

    const int tid  = threadIdx.x;
    const int gtid = blockIdx.x * NTHR + tid;
    const int stride = gridDim.x * NTHR;
    float* sTp = sS + tid * SSTR;
    ull*   whb = g_wh + gtid;
    ull*   h2b = g_h2 + gtid;

    unsigned mrow[9];
    #pragma unroll
    for (int i = 0; i < 9; i++) mrow[i] = __ldg(&g_mrow[i]);
    float c1r[3], c2r[3];
    #pragma unroll
    for (int h = 0; h < 3; h++) { c1r[h] = __ldg(&g_c12[h]); c2r[h] = __ldg(&g_c12[3+h]); }

    for (int b = gtid; b < B; b += stride) {

        // ================= layer-1 (rank-1 collapse): s1[h][i] =================
        {
            float og[9];
            #pragma unroll
            for (int n = 0; n < 9; n++) og[n] = g_obs[b*9 + n];
            #pragma unroll 1
            for (int h = 0; h < 3; h++) {
                const float c1h = c1r[h], c2h = c2r[h];
                float gg[9];
                #pragma unroll
                for (int j = 0; j < 9; j++) gg[j] = c2h * og[j];
                #pragma unroll
                for (int i = 0; i < 9; i++) {
                    const unsigned m = mrow[i];
                    const float fi = c1h * og[i];
                    float e[9], mx = -3.0e38f;
                    #pragma unroll
                    for (int j = 0; j < 9; j++) {
                        float x = lrelu(fi + gg[j]);
                        if (!((m >> j) & 1u)) x = MASKV;
                        e[j] = x; mx = fmaxf(mx, x);
                    }
                    float den = 0.f, num = 0.f;
                    #pragma unroll
                    for (int j = 0; j < 9; j++) {
                        float p = __expf(e[j] - mx);
                        den += p; num += p * og[j];
                    }
                    sTp[h*9 + i] = __fdividef(num, den);
                }
            }
        }

        // ================= layer-2 per head =================
        #pragma unroll 1
        for (int H = 0; H < 3; H++) {
            const float* wH = &cW2[H*1536];
            float f1a[9], f2a[9];

            // ---- GEMM in 3-row passes (W2 from constant, 16B loads) ----
            #pragma unroll 1
            for (int g3 = 0; g3 < 9; g3 += 3) {
                ull acc[3][8];
                #pragma unroll
                for (int r = 0; r < 3; r++)
                    #pragma unroll
                    for (int p = 0; p < 8; p++) acc[r][p] = 0ull;

                #pragma unroll 1
                for (int kh = 0; kh < 3; kh++) {
                    const float sA = sTp[kh*9 + g3];
                    const float sB = sTp[kh*9 + g3 + 1];
                    const float sC = sTp[kh*9 + g3 + 2];
                    #pragma unroll 4
                    for (int d = 0; d < 32; d++) {
                        const int k = kh*32 + d;
                        const float w1 = cW1[k];
                        const ull eA = dup2(elu(sA * w1));
                        const ull eB = dup2(elu(sB * w1));
                        const ull eC = dup2(elu(sC * w1));
                        const float* wr = wH + k*16;
                        const ull2 wa = *(const ull2*)(wr);
                        const ull2 wb = *(const ull2*)(wr + 4);
                        const ull2 wc = *(const ull2*)(wr + 8);
                        const ull2 wd = *(const ull2*)(wr + 12);
                        ffma2(acc[0][0], eA, wa.x); ffma2(acc[0][1], eA, wa.y);
                        ffma2(acc[0][2], eA, wb.x); ffma2(acc[0][3], eA, wb.y);
                        ffma2(acc[0][4], eA, wc.x); ffma2(acc[0][5], eA, wc.y);
                        ffma2(acc[0][6], eA, wd.x); ffma2(acc[0][7], eA, wd.y);
                        ffma2(acc[1][0], eB, wa.x); ffma2(acc[1][1], eB, wa.y);
                        ffma2(acc[1][2], eB, wb.x); ffma2(acc[1][3], eB, wb.y);
                        ffma2(acc[1][4], eB, wc.x); ffma2(acc[1][5], eB, wc.y);
                        ffma2(acc[1][6], eB, wd.x); ffma2(acc[1][7], eB, wd.y);
                        ffma2(acc[2][0], eC, wa.x); ffma2(acc[2][1], eC, wa.y);
                        ffma2(acc[2][2], eC, wb.x); ffma2(acc[2][3], eC, wb.y);
                        ffma2(acc[2][4], eC, wc.x); ffma2(acc[2][5], eC, wc.y);
                        ffma2(acc[2][6], eC, wd.x); ffma2(acc[2][7], eC, wd.y);
                    }
                }
                #pragma unroll
                for (int r = 0; r < 3; r++) {
                    float f1 = 0.f, f2 = 0.f;
                    #pragma unroll
                    for (int p = 0; p < 8; p++) {
                        float2 t = unp(acc[r][p]);
                        f1 += t.x * cA2[H*32 + 2*p]      + t.y * cA2[H*32 + 2*p + 1];
                        f2 += t.x * cA2[H*32 + 16 + 2*p] + t.y * cA2[H*32 + 17 + 2*p];
                    }
                    f1a[g3 + r] = f1;
                    f2a[g3 + r] = f2;
                    #pragma unroll
                    for (int p = 0; p < 8; p++)
                        whb[((g3 + r)*8 + p)*NT] = acc[r][p];
                }
            }

            // ---- attention apply for head H ----
            #pragma unroll 1
            for (int i = 0; i < 9; i++) {
                const unsigned m = mrow[i];
                const float f1i = f1a[i];
                float e[9], mx = -3.0e38f;
                #pragma unroll
                for (int j = 0; j < 9; j++) {
                    float x = lrelu(f1i + f2a[j]);
                    if (!((m >> j) & 1u)) x = MASKV;
                    e[j] = x; mx = fmaxf(mx, x);
                }
                float den = 0.f;
                #pragma unroll
                for (int j = 0; j < 9; j++) { e[j] = __expf(e[j] - mx); den += e[j]; }
                const float inv = __fdividef(1.f, den);

                ull h2a[8];
                #pragma unroll
                for (int p = 0; p < 8; p++) h2a[p] = 0ull;
                #pragma unroll
                for (int j = 0; j < 9; j++) {
                    const ull wd = dup2(e[j] * inv);
                    #pragma unroll
                    for (int p = 0; p < 8; p++)
                        ffma2(h2a[p], whb[(j*8 + p)*NT], wd);
                }
                #pragma unroll
                for (int p = 0; p < 8; p++)
                    h2b[(i*24 + H*8 + p)*NT] = h2a[p];
            }
        }

        // ================= pooling =================
        float scl[9];
        #pragma unroll 1
        for (int n = 0; n < 9; n++) {
            ull U[12];
            #pragma unroll
            for (int mp = 0; mp < 12; mp++) U[mp] = c64(&cBp1[2*mp]);
            #pragma unroll 4
            for (int cp = 0; cp < 24; cp++) {
                float2 hv = unp(h2b[(n*24 + cp)*NT]);
                ull hx = dup2(hv.x), hy = dup2(hv.y);
                #pragma unroll
                for (int mq = 0; mq < 6; mq++) {
                    ull2 wa = *(const ull2*)&cWp1[(2*cp    )*24 + 4*mq];
                    ull2 wb = *(const ull2*)&cWp1[(2*cp + 1)*24 + 4*mq];
                    ffma2(U[2*mq],     hx, wa.x);
                    ffma2(U[2*mq + 1], hx, wa.y);
                    ffma2(U[2*mq],     hy, wb.x);
                    ffma2(U[2*mq + 1], hy, wb.y);
                }
            }
            float s = cBp2[0];
            #pragma unroll
            for (int mp = 0; mp < 12; mp++) {
                float2 u = unp(U[mp]);
                s += tanh_fast(u.x) * cWp2[2*mp] + tanh_fast(u.y) * cWp2[2*mp + 1];
            }
            scl[n] = s;
        }

        // softmax over nodes
        float mx = scl[0];
        #pragma unroll
        for (int n = 1; n < 9; n++) mx = fmaxf(mx, scl[n]);
        float den = 0.f, wnl[9];
        #pragma unroll
        for (int n = 0; n < 9; n++) { float p = __expf(scl[n] - mx); wnl[n] = p; den += p; }
        const float iv = __fdividef(1.f, den);

        ull outp[24];
        #pragma unroll
        for (int p = 0; p < 24; p++) outp[p] = 0ull;
        #pragma unroll 1
        for (int n = 0; n < 9; n++) {
            const ull wd = dup2(wnl[n] * iv);
            #pragma unroll
            for (int p = 0; p < 24; p++)
                ffma2(outp[p], h2b[(n*24 + p)*NT], wd);
        }
        #pragma unroll
        for (int p = 0; p < 24; p++)
            *(ull*)&g_out[(size_t)b*48 + 2*p] = outp[p];
    }
}

extern "C" void kernel_launch(void* const* d_in, const int* in_sizes, int n_in,
                              void* d_out, int out_size) {
    const float* obs = (const float*)d_in[0];
    int B = in_sizes[0] / 9;

    cudaMemcpyToSymbolAsync(cAdj, d_in[1],   81 * 4, 0, cudaMemcpyDeviceToDevice);
    cudaMemcpyToSymbolAsync(cW1,  d_in[2],   96 * 4, 0, cudaMemcpyDeviceToDevice);
    cudaMemcpyToSymbolAsync(cA1,  d_in[3],  192 * 4, 0, cudaMemcpyDeviceToDevice);
    cudaMemcpyToSymbolAsync(cW2,  d_in[4], 4608 * 4, 0, cudaMemcpyDeviceToDevice);
    cudaMemcpyToSymbolAsync(cA2,  d_in[5],   96 * 4, 0, cudaMemcpyDeviceToDevice);
    cudaMemcpyToSymbolAsync(cWp1, d_in[6], 1152 * 4, 0, cudaMemcpyDeviceToDevice);
    cudaMemcpyToSymbolAsync(cBp1, d_in[7],   24 * 4, 0, cudaMemcpyDeviceToDevice);
    cudaMemcpyToSymbolAsync(cWp2, d_in[8],   24 * 4, 0, cudaMemcpyDeviceToDevice);
    cudaMemcpyToSymbolAsync(cBp2, d_in[9],    1 * 4, 0, cudaMemcpyDeviceToDevice);

    int blocks = (B + NTHR - 1) / NTHR;
    if (blocks > MAXBLK) blocks = MAXBLK;

    prep_kernel<<<1, 32>>>();
    gnn_main<<<blocks, NTHR>>>(obs, (float*)d_out, B);
}